// round 1
// baseline (speedup 1.0000x reference)
#include <cuda_runtime.h>

// Problem constants
#define B_  2
#define S_  2048
#define D_  1024
#define H_  16
#define DH_ 64
#define M_  (B_*S_)          // 4096 rows total

// Scratch (allocation-free): Q,K,V head-major [B,H,S,DH], ctx row-major [B,S,D]
__device__ float g_Q[(size_t)B_*S_*D_];
__device__ float g_K[(size_t)B_*S_*D_];
__device__ float g_V[(size_t)B_*S_*D_];
__device__ float g_ctx[(size_t)B_*S_*D_];

// ---------------------------------------------------------------------------
// Tiled SGEMM: C[m,n] = sum_k A[m,k] * W[n,k]  (+ bias in MODE 1)
// 128x128 block tile, BK=16, 256 threads, 8x8 per-thread micro-tile.
// MODE 0: store head-major split  out[((b*H+h)*S+s)*DH+dh]
// MODE 1: store row-major + bias  out[m*D+n]
// ---------------------------------------------------------------------------
template<int MODE>
__global__ __launch_bounds__(256) void gemm128(const float* __restrict__ A,
                                               const float* __restrict__ W,
                                               const float* __restrict__ bias,
                                               float* __restrict__ out)
{
    __shared__ float As[16][132];   // stored transposed: As[k][m]
    __shared__ float Bs[16][132];   // stored transposed: Bs[k][n]

    const int tid = threadIdx.x;
    const int tx  = tid & 15;       // 16 col groups
    const int ty  = tid >> 4;       // 16 row groups
    const int m0  = blockIdx.y * 128;
    const int n0  = blockIdx.x * 128;

    float acc[8][8];
#pragma unroll
    for (int i = 0; i < 8; i++)
#pragma unroll
        for (int j = 0; j < 8; j++) acc[i][j] = 0.f;

    for (int k0 = 0; k0 < D_; k0 += 16) {
#pragma unroll
        for (int i = 0; i < 2; i++) {
            int f   = tid * 2 + i;          // 0..511
            int row = f >> 2;               // 0..127
            int c4  = (f & 3) * 4;          // 0,4,8,12
            float4 va = *(const float4*)(A + (size_t)(m0 + row) * D_ + k0 + c4);
            As[c4+0][row] = va.x; As[c4+1][row] = va.y;
            As[c4+2][row] = va.z; As[c4+3][row] = va.w;
            float4 vb = *(const float4*)(W + (size_t)(n0 + row) * D_ + k0 + c4);
            Bs[c4+0][row] = vb.x; Bs[c4+1][row] = vb.y;
            Bs[c4+2][row] = vb.z; Bs[c4+3][row] = vb.w;
        }
        __syncthreads();
#pragma unroll
        for (int kk = 0; kk < 16; kk++) {
            float a[8], b[8];
            *(float4*)&a[0] = *(const float4*)&As[kk][ty*8];
            *(float4*)&a[4] = *(const float4*)&As[kk][ty*8+4];
            *(float4*)&b[0] = *(const float4*)&Bs[kk][tx*8];
            *(float4*)&b[4] = *(const float4*)&Bs[kk][tx*8+4];
#pragma unroll
            for (int i = 0; i < 8; i++)
#pragma unroll
                for (int j = 0; j < 8; j++)
                    acc[i][j] = fmaf(a[i], b[j], acc[i][j]);
        }
        __syncthreads();
    }

#pragma unroll
    for (int i = 0; i < 8; i++) {
        int m = m0 + ty * 8 + i;
        int n = n0 + tx * 8;                 // 8 contiguous cols, within one head
        if (MODE == 1) {
            float r[8];
#pragma unroll
            for (int j = 0; j < 8; j++) r[j] = acc[i][j] + bias[n + j];
            float4* dst = (float4*)(out + (size_t)m * D_ + n);
            dst[0] = make_float4(r[0], r[1], r[2], r[3]);
            dst[1] = make_float4(r[4], r[5], r[6], r[7]);
        } else {
            int bb = m >> 11;                // m / S_  (S_=2048)
            int s  = m & (S_ - 1);
            int h  = n >> 6;                 // n / DH_
            int dh = n & (DH_ - 1);
            float4* dst = (float4*)(out + (size_t)((bb * H_ + h) * S_ + s) * DH_ + dh);
            dst[0] = make_float4(acc[i][0], acc[i][1], acc[i][2], acc[i][3]);
            dst[1] = make_float4(acc[i][4], acc[i][5], acc[i][6], acc[i][7]);
        }
    }
}

// ---------------------------------------------------------------------------
// Flash-style causal attention, one block per (q-tile of 64 rows, b*H pair).
// BLOCK_M = BLOCK_N = DH = 64, 128 threads (16x8), per-thread 4x8 micro-tiles.
// Online softmax; ctx written row-major [B,S,D].
// ---------------------------------------------------------------------------
#define ATT_LD 65   // row stride (pad to dodge 32-bank conflicts on row reads)

__global__ __launch_bounds__(128) void attn_causal()
{
    extern __shared__ float sm[];
    float* Qs = sm;                       // [64][ATT_LD]
    float* Ks = Qs + 64 * ATT_LD;
    float* Vs = Ks + 64 * ATT_LD;
    float* Ps = Vs + 64 * ATT_LD;

    const int tid = threadIdx.x;
    const int tx  = tid & 7;              // 8 col groups (8 cols each)
    const int ty  = tid >> 3;             // 16 row groups (4 rows each)
    const int qt  = blockIdx.x;           // q tile index
    const int bh  = blockIdx.y;           // b*H + h
    const int q0  = qt * 64;

    const float* Qp = g_Q + (size_t)bh * S_ * DH_;
    const float* Kp = g_K + (size_t)bh * S_ * DH_;
    const float* Vp = g_V + (size_t)bh * S_ * DH_;

    // Load Q tile once
    for (int idx = tid; idx < 64 * 16; idx += 128) {
        int r = idx >> 4, c = (idx & 15) * 4;
        float4 v = *(const float4*)(Qp + (size_t)(q0 + r) * DH_ + c);
        Qs[r*ATT_LD + c+0] = v.x; Qs[r*ATT_LD + c+1] = v.y;
        Qs[r*ATT_LD + c+2] = v.z; Qs[r*ATT_LD + c+3] = v.w;
    }

    float m_i[4], l_i[4], o[4][8];
#pragma unroll
    for (int i = 0; i < 4; i++) {
        m_i[i] = -1e30f; l_i[i] = 0.f;
#pragma unroll
        for (int j = 0; j < 8; j++) o[i][j] = 0.f;
    }
    __syncthreads();

    for (int kt = 0; kt <= qt; kt++) {
        const int k0 = kt * 64;
        for (int idx = tid; idx < 64 * 16; idx += 128) {
            int r = idx >> 4, c = (idx & 15) * 4;
            float4 vk = *(const float4*)(Kp + (size_t)(k0 + r) * DH_ + c);
            Ks[r*ATT_LD + c+0] = vk.x; Ks[r*ATT_LD + c+1] = vk.y;
            Ks[r*ATT_LD + c+2] = vk.z; Ks[r*ATT_LD + c+3] = vk.w;
            float4 vv = *(const float4*)(Vp + (size_t)(k0 + r) * DH_ + c);
            Vs[r*ATT_LD + c+0] = vv.x; Vs[r*ATT_LD + c+1] = vv.y;
            Vs[r*ATT_LD + c+2] = vv.z; Vs[r*ATT_LD + c+3] = vv.w;
        }
        __syncthreads();

        // S = Q @ K^T  (per-thread 4x8)
        float s[4][8];
#pragma unroll
        for (int i = 0; i < 4; i++)
#pragma unroll
            for (int j = 0; j < 8; j++) s[i][j] = 0.f;
        for (int kk = 0; kk < 64; kk++) {
            float a[4], b[8];
#pragma unroll
            for (int i = 0; i < 4; i++) a[i] = Qs[(ty*4 + i)*ATT_LD + kk];
#pragma unroll
            for (int j = 0; j < 8; j++) b[j] = Ks[(tx*8 + j)*ATT_LD + kk];
#pragma unroll
            for (int i = 0; i < 4; i++)
#pragma unroll
                for (int j = 0; j < 8; j++)
                    s[i][j] = fmaf(a[i], b[j], s[i][j]);
        }

        // scale + causal mask (only needed on the diagonal tile)
        const float scale = 0.125f;       // 1/sqrt(64)
        const bool diag = (kt == qt);
#pragma unroll
        for (int i = 0; i < 4; i++) {
            int qrow = q0 + ty*4 + i;
#pragma unroll
            for (int j = 0; j < 8; j++) {
                float v = s[i][j] * scale;
                if (diag && (k0 + tx*8 + j) > qrow) v = -1e30f;
                s[i][j] = v;
            }
        }

        // online softmax update (row reductions across the 8 tx lanes)
#pragma unroll
        for (int i = 0; i < 4; i++) {
            float rm = s[i][0];
#pragma unroll
            for (int j = 1; j < 8; j++) rm = fmaxf(rm, s[i][j]);
            rm = fmaxf(rm, __shfl_xor_sync(0xffffffffu, rm, 1));
            rm = fmaxf(rm, __shfl_xor_sync(0xffffffffu, rm, 2));
            rm = fmaxf(rm, __shfl_xor_sync(0xffffffffu, rm, 4));
            float mnew  = fmaxf(m_i[i], rm);
            float alpha = __expf(m_i[i] - mnew);
            float rs = 0.f;
#pragma unroll
            for (int j = 0; j < 8; j++) {
                float p = __expf(s[i][j] - mnew);
                Ps[(ty*4 + i)*ATT_LD + tx*8 + j] = p;
                rs += p;
            }
            rs += __shfl_xor_sync(0xffffffffu, rs, 1);
            rs += __shfl_xor_sync(0xffffffffu, rs, 2);
            rs += __shfl_xor_sync(0xffffffffu, rs, 4);
            l_i[i] = l_i[i] * alpha + rs;
            m_i[i] = mnew;
#pragma unroll
            for (int j = 0; j < 8; j++) o[i][j] *= alpha;
        }
        __syncthreads();                  // Ps visible to all threads

        // O += P @ V
        for (int kk = 0; kk < 64; kk++) {
            float p4[4], v8[8];
#pragma unroll
            for (int i = 0; i < 4; i++) p4[i] = Ps[(ty*4 + i)*ATT_LD + kk];
#pragma unroll
            for (int j = 0; j < 8; j++) v8[j] = Vs[kk*ATT_LD + tx*8 + j];
#pragma unroll
            for (int i = 0; i < 4; i++)
#pragma unroll
                for (int j = 0; j < 8; j++)
                    o[i][j] = fmaf(p4[i], v8[j], o[i][j]);
        }
        __syncthreads();                  // Ks/Vs/Ps free for next tile
    }

    // normalize + write ctx row-major [B,S,D]
    const int b = bh >> 4, h = bh & (H_ - 1);
#pragma unroll
    for (int i = 0; i < 4; i++) {
        float inv = 1.f / l_i[i];
        float* dst = g_ctx + (size_t)(b * S_ + q0 + ty*4 + i) * D_ + h * DH_ + tx*8;
#pragma unroll
        for (int j = 0; j < 8; j++) dst[j] = o[i][j] * inv;
    }
}

// ---------------------------------------------------------------------------
extern "C" void kernel_launch(void* const* d_in, const int* in_sizes, int n_in,
                              void* d_out, int out_size)
{
    const float* x  = (const float*)d_in[0];
    const float* Wq = (const float*)d_in[1];
    const float* Wk = (const float*)d_in[2];
    const float* Wv = (const float*)d_in[3];
    const float* Wo = (const float*)d_in[4];
    const float* bo = (const float*)d_in[5];
    float* out = (float*)d_out;

    float *q, *k, *v, *ctx;
    cudaGetSymbolAddress((void**)&q,   g_Q);
    cudaGetSymbolAddress((void**)&k,   g_K);
    cudaGetSymbolAddress((void**)&v,   g_V);
    cudaGetSymbolAddress((void**)&ctx, g_ctx);

    dim3 ggrid(D_/128, M_/128);   // (8, 32)

    gemm128<0><<<ggrid, 256>>>(x, Wq, nullptr, q);
    gemm128<0><<<ggrid, 256>>>(x, Wk, nullptr, k);
    gemm128<0><<<ggrid, 256>>>(x, Wv, nullptr, v);

    const int smem = 4 * 64 * ATT_LD * (int)sizeof(float);   // 66560 B
    cudaFuncSetAttribute(attn_causal, cudaFuncAttributeMaxDynamicSharedMemorySize, smem);
    attn_causal<<<dim3(S_/64, B_*H_), 128, smem>>>();

    gemm128<1><<<ggrid, 256>>>(ctx, Wo, bo, out);
}

// round 3
// speedup vs baseline: 1.5338x; 1.5338x over previous
#include <cuda_runtime.h>
#include <cuda_bf16.h>
#include <cstdint>

// Problem constants
#define B_  2
#define S_  2048
#define D_  1024
#define H_  16
#define DH_ 64
#define M_  (B_*S_)          // 4096 rows total

// ---------------------------------------------------------------------------
// Scratch (allocation-free __device__ globals)
// ---------------------------------------------------------------------------
__device__ float g_Q[(size_t)B_*S_*D_];     // head-major [B,H,S,DH]
__device__ float g_K[(size_t)B_*S_*D_];
__device__ float g_V[(size_t)B_*S_*D_];
__device__ float g_ctx[(size_t)B_*S_*D_];   // row-major [B,S,D]

__device__ __nv_bfloat16 g_xhi[(size_t)M_*D_];
__device__ __nv_bfloat16 g_xlo[(size_t)M_*D_];
__device__ __nv_bfloat16 g_whi[(size_t)4*D_*D_];
__device__ __nv_bfloat16 g_wlo[(size_t)4*D_*D_];
__device__ __nv_bfloat16 g_chi[(size_t)M_*D_];
__device__ __nv_bfloat16 g_clo[(size_t)M_*D_];

// ---------------------------------------------------------------------------
// Small PTX helpers (all plain sm_80-class PTX: valid under compute_103)
// ---------------------------------------------------------------------------
__device__ __forceinline__ uint32_t smem_u32(const void* p) {
    uint32_t a;
    asm("{ .reg .u64 t; cvta.to.shared.u64 t, %1; cvt.u32.u64 %0, t; }"
        : "=r"(a) : "l"(p));
    return a;
}
__device__ __forceinline__ void cp16(uint32_t dst, const void* src) {
    asm volatile("cp.async.cg.shared.global [%0], [%1], 16;"
                 :: "r"(dst), "l"(src) : "memory");
}
__device__ __forceinline__ void cp_commit() {
    asm volatile("cp.async.commit_group;" ::: "memory");
}
__device__ __forceinline__ void cp_wait0() {
    asm volatile("cp.async.wait_group 0;" ::: "memory");
}
__device__ __forceinline__ void ldsm4(uint32_t& r0, uint32_t& r1, uint32_t& r2,
                                      uint32_t& r3, uint32_t addr) {
    asm volatile("ldmatrix.sync.aligned.m8n8.x4.shared.b16 {%0,%1,%2,%3}, [%4];"
                 : "=r"(r0), "=r"(r1), "=r"(r2), "=r"(r3) : "r"(addr));
}
__device__ __forceinline__ void mma16816(float* c, const uint32_t* a, const uint32_t* b) {
    asm volatile(
        "mma.sync.aligned.m16n8k16.row.col.f32.bf16.bf16.f32 "
        "{%0,%1,%2,%3}, {%4,%5,%6,%7}, {%8,%9}, {%0,%1,%2,%3};"
        : "+f"(c[0]), "+f"(c[1]), "+f"(c[2]), "+f"(c[3])
        : "r"(a[0]), "r"(a[1]), "r"(a[2]), "r"(a[3]), "r"(b[0]), "r"(b[1]));
}
// Swizzle<3,4,3>: XOR 16B-column bits [6:4] with row bits [9:7]
__device__ __forceinline__ uint32_t swz(uint32_t off) {
    return off ^ ((off >> 3) & 0x70);
}

// ---------------------------------------------------------------------------
// fp32 -> bf16 hi/lo split (error-compensated)
// ---------------------------------------------------------------------------
__global__ void split_bf16(const float* __restrict__ src,
                           __nv_bfloat16* __restrict__ hi,
                           __nv_bfloat16* __restrict__ lo, int n)
{
    int i = (blockIdx.x * blockDim.x + threadIdx.x) * 2;
    if (i < n) {
        float2 v = *(const float2*)(src + i);
        __nv_bfloat16 h0 = __float2bfloat16(v.x);
        __nv_bfloat16 h1 = __float2bfloat16(v.y);
        __nv_bfloat16 l0 = __float2bfloat16(v.x - __bfloat162float(h0));
        __nv_bfloat16 l1 = __float2bfloat16(v.y - __bfloat162float(h1));
        *(__nv_bfloat162*)(hi + i) = __halves2bfloat162(h0, h1);
        *(__nv_bfloat162*)(lo + i) = __halves2bfloat162(l0, l1);
    }
}

// ---------------------------------------------------------------------------
// HMMA bf16x3 GEMM: C[m,n] = sum_k A[m,k]*W[n,k]   (A,W split hi/lo)
// 128x128 CTA tile, BK=64, 256 threads (8 warps = 2m x 4n, warp tile 64x32).
// cp.async double-buffered smem; ldmatrix.x4 loads; mma.m16n8k16 bf16.
// MODE 0: store head-major split  out[((b*H+h)*S+s)*DH+dh]
// MODE 1: store row-major + bias  out[m*D+n]
// ---------------------------------------------------------------------------
#define TILE_B  16384               // one 128x64 bf16 tile = 16 KB
#define STAGE_B (4*TILE_B)          // Ahi,Alo,Bhi,Blo = 64 KB
#define TG_SMEM (2*STAGE_B)         // double buffer = 128 KB
#define NCHUNK  (D_/64)             // 16

template<int MODE>
__global__ __launch_bounds__(256, 1) void tgemm(const __nv_bfloat16* __restrict__ Ahi,
                                                const __nv_bfloat16* __restrict__ Alo,
                                                const __nv_bfloat16* __restrict__ Bhi,
                                                const __nv_bfloat16* __restrict__ Blo,
                                                const float* __restrict__ bias,
                                                float* __restrict__ out)
{
    extern __shared__ char smem[];
    const uint32_t sb = smem_u32(smem);
    const int tid  = threadIdx.x;
    const int wid  = tid >> 5;
    const int lane = tid & 31;
    const int wm   = wid >> 2;          // 0..1  (64-row slab)
    const int wn   = wid & 3;           // 0..3  (32-col slab)
    const int m0   = blockIdx.y * 128;
    const int n0   = blockIdx.x * 128;

    const char* gsrc[4] = {
        (const char*)(Ahi + (size_t)m0 * D_),
        (const char*)(Alo + (size_t)m0 * D_),
        (const char*)(Bhi + (size_t)n0 * D_),
        (const char*)(Blo + (size_t)n0 * D_) };

    // per-thread load slot: 4 iters x 4 tiles, 16B each
    const int lrow = tid >> 1;                   // 0..127 (two 16B per row half? no:)
    // 1024 16B-chunks per tile; thread does chunks tid, tid+256, tid+512, tid+768
    auto load_stage = [&](int chunk, uint32_t stage_base) {
        const uint32_t koff = (uint32_t)chunk * 128;   // byte offset along K
#pragma unroll
        for (int t = 0; t < 4; ++t) {
            const char* base = gsrc[t] + koff;
            const uint32_t dstt = stage_base + t * TILE_B;
#pragma unroll
            for (int it = 0; it < 4; ++it) {
                const int c = tid + it * 256;     // 0..1023
                const int r = c >> 3;             // row 0..127
                const int c16 = c & 7;            // 16B col 0..7
                cp16(dstt + swz((uint32_t)(r * 128 + c16 * 16)),
                     base + (size_t)r * (D_ * 2) + c16 * 16);
            }
        }
        cp_commit();
    };

    float acc[4][4][4];
#pragma unroll
    for (int i = 0; i < 4; i++)
#pragma unroll
        for (int j = 0; j < 4; j++)
#pragma unroll
            for (int q = 0; q < 4; q++) acc[i][j][q] = 0.f;

    load_stage(0, sb);

    for (int c = 0; c < NCHUNK; ++c) {
        cp_wait0();
        __syncthreads();
        const uint32_t cur = sb + (c & 1) * STAGE_B;
        if (c + 1 < NCHUNK) load_stage(c + 1, sb + ((c + 1) & 1) * STAGE_B);

        const uint32_t aHi = cur;
        const uint32_t aLo = cur + TILE_B;
        const uint32_t bHi = cur + 2 * TILE_B;
        const uint32_t bLo = cur + 3 * TILE_B;

#pragma unroll
        for (int ks = 0; ks < 4; ++ks) {
            // ---- A fragments (4 x m16k16) for hi and lo ----
            uint32_t ahi[4][4], alo[4][4];
            {
                const int rA = wm * 64 + (lane & 15);
                const uint32_t colA = (uint32_t)(ks * 32 + (lane >> 4) * 16);
#pragma unroll
                for (int mf = 0; mf < 4; ++mf) {
                    const int row = rA + mf * 16;
                    const uint32_t off = swz((uint32_t)row * 128 + colA);
                    ldsm4(ahi[mf][0], ahi[mf][1], ahi[mf][2], ahi[mf][3], aHi + off);
                    ldsm4(alo[mf][0], alo[mf][1], alo[mf][2], alo[mf][3], aLo + off);
                }
            }
            // ---- B fragments (4 x n8k16) for hi and lo ----
            uint32_t bhi[4][2], blo[4][2];
            {
                const int t = lane >> 3;                   // tile 0..3
                const int rB0 = wn * 32 + ((t >> 1) * 8) + (lane & 7);
                const uint32_t colB = (uint32_t)(ks * 32 + (t & 1) * 16);
#pragma unroll
                for (int p = 0; p < 2; ++p) {              // n16 halves
                    const int row = rB0 + p * 16;
                    const uint32_t off = swz((uint32_t)row * 128 + colB);
                    ldsm4(bhi[2*p][0], bhi[2*p][1], bhi[2*p+1][0], bhi[2*p+1][1], bHi + off);
                    ldsm4(blo[2*p][0], blo[2*p][1], blo[2*p+1][0], blo[2*p+1][1], bLo + off);
                }
            }
            // ---- 3-term compensated MMA ----
#pragma unroll
            for (int mf = 0; mf < 4; ++mf)
#pragma unroll
                for (int nf = 0; nf < 4; ++nf) {
                    mma16816(acc[mf][nf], ahi[mf], bhi[nf]);
                    mma16816(acc[mf][nf], ahi[mf], blo[nf]);
                    mma16816(acc[mf][nf], alo[mf], bhi[nf]);
                }
        }
        __syncthreads();
    }

    // ---- epilogue ----
    const int gid = lane >> 2, tig = lane & 3;
#pragma unroll
    for (int mf = 0; mf < 4; ++mf)
#pragma unroll
        for (int nf = 0; nf < 4; ++nf)
#pragma unroll
            for (int half = 0; half < 2; ++half) {
                const int m = m0 + wm * 64 + mf * 16 + gid + half * 8;
                const int n = n0 + wn * 32 + nf * 8 + tig * 2;
                float2 v = make_float2(acc[mf][nf][half*2], acc[mf][nf][half*2+1]);
                if (MODE == 1) {
                    v.x += bias[n]; v.y += bias[n+1];
                    *(float2*)(out + (size_t)m * D_ + n) = v;
                } else {
                    const int b  = m >> 11;          // m / S_
                    const int s  = m & (S_ - 1);
                    const int h  = n >> 6;
                    const int dh = n & (DH_ - 1);
                    *(float2*)(out + ((size_t)(b * H_ + h) * S_ + s) * DH_ + dh) = v;
                }
            }
}

// ---------------------------------------------------------------------------
// Flash-style causal attention (unchanged from R1 baseline)
// ---------------------------------------------------------------------------
#define ATT_LD 65

__global__ __launch_bounds__(128) void attn_causal()
{
    extern __shared__ float sm[];
    float* Qs = sm;
    float* Ks = Qs + 64 * ATT_LD;
    float* Vs = Ks + 64 * ATT_LD;
    float* Ps = Vs + 64 * ATT_LD;

    const int tid = threadIdx.x;
    const int tx  = tid & 7;
    const int ty  = tid >> 3;
    const int qt  = blockIdx.x;
    const int bh  = blockIdx.y;
    const int q0  = qt * 64;

    const float* Qp = g_Q + (size_t)bh * S_ * DH_;
    const float* Kp = g_K + (size_t)bh * S_ * DH_;
    const float* Vp = g_V + (size_t)bh * S_ * DH_;

    for (int idx = tid; idx < 64 * 16; idx += 128) {
        int r = idx >> 4, c = (idx & 15) * 4;
        float4 v = *(const float4*)(Qp + (size_t)(q0 + r) * DH_ + c);
        Qs[r*ATT_LD + c+0] = v.x; Qs[r*ATT_LD + c+1] = v.y;
        Qs[r*ATT_LD + c+2] = v.z; Qs[r*ATT_LD + c+3] = v.w;
    }

    float m_i[4], l_i[4], o[4][8];
#pragma unroll
    for (int i = 0; i < 4; i++) {
        m_i[i] = -1e30f; l_i[i] = 0.f;
#pragma unroll
        for (int j = 0; j < 8; j++) o[i][j] = 0.f;
    }
    __syncthreads();

    for (int kt = 0; kt <= qt; kt++) {
        const int k0 = kt * 64;
        for (int idx = tid; idx < 64 * 16; idx += 128) {
            int r = idx >> 4, c = (idx & 15) * 4;
            float4 vk = *(const float4*)(Kp + (size_t)(k0 + r) * DH_ + c);
            Ks[r*ATT_LD + c+0] = vk.x; Ks[r*ATT_LD + c+1] = vk.y;
            Ks[r*ATT_LD + c+2] = vk.z; Ks[r*ATT_LD + c+3] = vk.w;
            float4 vv = *(const float4*)(Vp + (size_t)(k0 + r) * DH_ + c);
            Vs[r*ATT_LD + c+0] = vv.x; Vs[r*ATT_LD + c+1] = vv.y;
            Vs[r*ATT_LD + c+2] = vv.z; Vs[r*ATT_LD + c+3] = vv.w;
        }
        __syncthreads();

        float s[4][8];
#pragma unroll
        for (int i = 0; i < 4; i++)
#pragma unroll
            for (int j = 0; j < 8; j++) s[i][j] = 0.f;
        for (int kk = 0; kk < 64; kk++) {
            float a[4], b[8];
#pragma unroll
            for (int i = 0; i < 4; i++) a[i] = Qs[(ty*4 + i)*ATT_LD + kk];
#pragma unroll
            for (int j = 0; j < 8; j++) b[j] = Ks[(tx*8 + j)*ATT_LD + kk];
#pragma unroll
            for (int i = 0; i < 4; i++)
#pragma unroll
                for (int j = 0; j < 8; j++)
                    s[i][j] = fmaf(a[i], b[j], s[i][j]);
        }

        const float scale = 0.125f;
        const bool diag = (kt == qt);
#pragma unroll
        for (int i = 0; i < 4; i++) {
            int qrow = q0 + ty*4 + i;
#pragma unroll
            for (int j = 0; j < 8; j++) {
                float v = s[i][j] * scale;
                if (diag && (k0 + tx*8 + j) > qrow) v = -1e30f;
                s[i][j] = v;
            }
        }

#pragma unroll
        for (int i = 0; i < 4; i++) {
            float rm = s[i][0];
#pragma unroll
            for (int j = 1; j < 8; j++) rm = fmaxf(rm, s[i][j]);
            rm = fmaxf(rm, __shfl_xor_sync(0xffffffffu, rm, 1));
            rm = fmaxf(rm, __shfl_xor_sync(0xffffffffu, rm, 2));
            rm = fmaxf(rm, __shfl_xor_sync(0xffffffffu, rm, 4));
            float mnew  = fmaxf(m_i[i], rm);
            float alpha = __expf(m_i[i] - mnew);
            float rs = 0.f;
#pragma unroll
            for (int j = 0; j < 8; j++) {
                float p = __expf(s[i][j] - mnew);
                Ps[(ty*4 + i)*ATT_LD + tx*8 + j] = p;
                rs += p;
            }
            rs += __shfl_xor_sync(0xffffffffu, rs, 1);
            rs += __shfl_xor_sync(0xffffffffu, rs, 2);
            rs += __shfl_xor_sync(0xffffffffu, rs, 4);
            l_i[i] = l_i[i] * alpha + rs;
            m_i[i] = mnew;
#pragma unroll
            for (int j = 0; j < 8; j++) o[i][j] *= alpha;
        }
        __syncthreads();

        for (int kk = 0; kk < 64; kk++) {
            float p4[4], v8[8];
#pragma unroll
            for (int i = 0; i < 4; i++) p4[i] = Ps[(ty*4 + i)*ATT_LD + kk];
#pragma unroll
            for (int j = 0; j < 8; j++) v8[j] = Vs[kk*ATT_LD + tx*8 + j];
#pragma unroll
            for (int i = 0; i < 4; i++)
#pragma unroll
                for (int j = 0; j < 8; j++)
                    o[i][j] = fmaf(p4[i], v8[j], o[i][j]);
        }
        __syncthreads();
    }

    const int b = bh >> 4, h = bh & (H_ - 1);
#pragma unroll
    for (int i = 0; i < 4; i++) {
        float inv = 1.f / l_i[i];
        float* dst = g_ctx + (size_t)(b * S_ + q0 + ty*4 + i) * D_ + h * DH_ + tx*8;
#pragma unroll
        for (int j = 0; j < 8; j++) dst[j] = o[i][j] * inv;
    }
}

// ---------------------------------------------------------------------------
extern "C" void kernel_launch(void* const* d_in, const int* in_sizes, int n_in,
                              void* d_out, int out_size)
{
    const float* x  = (const float*)d_in[0];
    const float* Wq = (const float*)d_in[1];
    const float* Wk = (const float*)d_in[2];
    const float* Wv = (const float*)d_in[3];
    const float* Wo = (const float*)d_in[4];
    const float* bo = (const float*)d_in[5];
    float* out = (float*)d_out;

    float *q, *k, *v, *ctx;
    __nv_bfloat16 *xhi, *xlo, *whi, *wlo, *chi, *clo;
    cudaGetSymbolAddress((void**)&q,   g_Q);
    cudaGetSymbolAddress((void**)&k,   g_K);
    cudaGetSymbolAddress((void**)&v,   g_V);
    cudaGetSymbolAddress((void**)&ctx, g_ctx);
    cudaGetSymbolAddress((void**)&xhi, g_xhi);
    cudaGetSymbolAddress((void**)&xlo, g_xlo);
    cudaGetSymbolAddress((void**)&whi, g_whi);
    cudaGetSymbolAddress((void**)&wlo, g_wlo);
    cudaGetSymbolAddress((void**)&chi, g_chi);
    cudaGetSymbolAddress((void**)&clo, g_clo);

    cudaFuncSetAttribute(tgemm<0>, cudaFuncAttributeMaxDynamicSharedMemorySize, TG_SMEM);
    cudaFuncSetAttribute(tgemm<1>, cudaFuncAttributeMaxDynamicSharedMemorySize, TG_SMEM);
    const int att_smem = 4 * 64 * ATT_LD * (int)sizeof(float);
    cudaFuncSetAttribute(attn_causal, cudaFuncAttributeMaxDynamicSharedMemorySize, att_smem);

    const int nx = M_ * D_;     // 4M elems
    const int nw = D_ * D_;     // 1M elems
    split_bf16<<<nx/512, 256>>>(x,  xhi, xlo, nx);
    split_bf16<<<nw/512, 256>>>(Wq, whi + 0*(size_t)nw, wlo + 0*(size_t)nw, nw);
    split_bf16<<<nw/512, 256>>>(Wk, whi + 1*(size_t)nw, wlo + 1*(size_t)nw, nw);
    split_bf16<<<nw/512, 256>>>(Wv, whi + 2*(size_t)nw, wlo + 2*(size_t)nw, nw);
    split_bf16<<<nw/512, 256>>>(Wo, whi + 3*(size_t)nw, wlo + 3*(size_t)nw, nw);

    dim3 ggrid(D_/128, M_/128);   // (8, 32)
    tgemm<0><<<ggrid, 256, TG_SMEM>>>(xhi, xlo, whi + 0*(size_t)nw, wlo + 0*(size_t)nw, nullptr, q);
    tgemm<0><<<ggrid, 256, TG_SMEM>>>(xhi, xlo, whi + 1*(size_t)nw, wlo + 1*(size_t)nw, nullptr, k);
    tgemm<0><<<ggrid, 256, TG_SMEM>>>(xhi, xlo, whi + 2*(size_t)nw, wlo + 2*(size_t)nw, nullptr, v);

    attn_causal<<<dim3(S_/64, B_*H_), 128, att_smem>>>();

    split_bf16<<<nx/512, 256>>>(ctx, chi, clo, nx);
    tgemm<1><<<ggrid, 256, TG_SMEM>>>(chi, clo, whi + 3*(size_t)nw, wlo + 3*(size_t)nw, bo, out);
}

// round 4
// speedup vs baseline: 3.5644x; 2.3238x over previous
#include <cuda_runtime.h>
#include <cuda_bf16.h>
#include <cstdint>

// Problem constants
#define B_  2
#define S_  2048
#define D_  1024
#define H_  16
#define DH_ 64
#define M_  (B_*S_)          // 4096 rows total

// ---------------------------------------------------------------------------
// Scratch (allocation-free __device__ globals), all bf16 hi/lo pairs
// ---------------------------------------------------------------------------
__device__ __nv_bfloat16 g_qhi[(size_t)B_*H_*S_*DH_];   // head-major
__device__ __nv_bfloat16 g_qlo[(size_t)B_*H_*S_*DH_];
__device__ __nv_bfloat16 g_khi[(size_t)B_*H_*S_*DH_];
__device__ __nv_bfloat16 g_klo[(size_t)B_*H_*S_*DH_];
__device__ __nv_bfloat16 g_vhi[(size_t)B_*H_*S_*DH_];
__device__ __nv_bfloat16 g_vlo[(size_t)B_*H_*S_*DH_];
__device__ __nv_bfloat16 g_chi[(size_t)M_*D_];          // ctx row-major
__device__ __nv_bfloat16 g_clo[(size_t)M_*D_];
__device__ __nv_bfloat16 g_xhi[(size_t)M_*D_];
__device__ __nv_bfloat16 g_xlo[(size_t)M_*D_];
__device__ __nv_bfloat16 g_whi[(size_t)4*D_*D_];
__device__ __nv_bfloat16 g_wlo[(size_t)4*D_*D_];

// ---------------------------------------------------------------------------
// PTX helpers (plain sm_80-class PTX: valid under compute_103)
// ---------------------------------------------------------------------------
__device__ __forceinline__ uint32_t smem_u32(const void* p) {
    uint32_t a;
    asm("{ .reg .u64 t; cvta.to.shared.u64 t, %1; cvt.u32.u64 %0, t; }"
        : "=r"(a) : "l"(p));
    return a;
}
__device__ __forceinline__ void cp16(uint32_t dst, const void* src) {
    asm volatile("cp.async.cg.shared.global [%0], [%1], 16;"
                 :: "r"(dst), "l"(src) : "memory");
}
__device__ __forceinline__ void cp_commit() {
    asm volatile("cp.async.commit_group;" ::: "memory");
}
__device__ __forceinline__ void cp_wait0() {
    asm volatile("cp.async.wait_group 0;" ::: "memory");
}
__device__ __forceinline__ void ldsm4(uint32_t& r0, uint32_t& r1, uint32_t& r2,
                                      uint32_t& r3, uint32_t addr) {
    asm volatile("ldmatrix.sync.aligned.m8n8.x4.shared.b16 {%0,%1,%2,%3}, [%4];"
                 : "=r"(r0), "=r"(r1), "=r"(r2), "=r"(r3) : "r"(addr));
}
__device__ __forceinline__ void ldsm4t(uint32_t& r0, uint32_t& r1, uint32_t& r2,
                                       uint32_t& r3, uint32_t addr) {
    asm volatile("ldmatrix.sync.aligned.m8n8.x4.trans.shared.b16 {%0,%1,%2,%3}, [%4];"
                 : "=r"(r0), "=r"(r1), "=r"(r2), "=r"(r3) : "r"(addr));
}
__device__ __forceinline__ void mma16816(float* c, const uint32_t* a, const uint32_t* b) {
    asm volatile(
        "mma.sync.aligned.m16n8k16.row.col.f32.bf16.bf16.f32 "
        "{%0,%1,%2,%3}, {%4,%5,%6,%7}, {%8,%9}, {%0,%1,%2,%3};"
        : "+f"(c[0]), "+f"(c[1]), "+f"(c[2]), "+f"(c[3])
        : "r"(a[0]), "r"(a[1]), "r"(a[2]), "r"(a[3]), "r"(b[0]), "r"(b[1]));
}
__device__ __forceinline__ float ex2(float x) {
    float y; asm("ex2.approx.ftz.f32 %0, %1;" : "=f"(y) : "f"(x)); return y;
}
// Swizzle<3,4,3>: XOR 16B-column bits [6:4] with row bits [9:7]
__device__ __forceinline__ uint32_t swz(uint32_t off) {
    return off ^ ((off >> 3) & 0x70);
}
__device__ __forceinline__ uint32_t packbf(__nv_bfloat16 a, __nv_bfloat16 b) {
    __nv_bfloat162 h = __halves2bfloat162(a, b);
    return *(uint32_t*)&h;
}

// ---------------------------------------------------------------------------
// fp32 -> bf16 hi/lo split (error-compensated)
// ---------------------------------------------------------------------------
__global__ void split_bf16(const float* __restrict__ src,
                           __nv_bfloat16* __restrict__ hi,
                           __nv_bfloat16* __restrict__ lo, int n)
{
    int i = (blockIdx.x * blockDim.x + threadIdx.x) * 2;
    if (i < n) {
        float2 v = *(const float2*)(src + i);
        __nv_bfloat16 h0 = __float2bfloat16(v.x);
        __nv_bfloat16 h1 = __float2bfloat16(v.y);
        __nv_bfloat16 l0 = __float2bfloat16(v.x - __bfloat162float(h0));
        __nv_bfloat16 l1 = __float2bfloat16(v.y - __bfloat162float(h1));
        *(__nv_bfloat162*)(hi + i) = __halves2bfloat162(h0, h1);
        *(__nv_bfloat162*)(lo + i) = __halves2bfloat162(l0, l1);
    }
}

// ---------------------------------------------------------------------------
// HMMA bf16x3 GEMM: C[m,n] = sum_k A[m,k]*W[n,k]   (A,W split hi/lo)
// 128x128 CTA tile, BK=64, 256 threads (8 warps = 2m x 4n, warp tile 64x32).
// MODE 0: store bf16 hi/lo head-major   ohi/olo[((b*H+h)*S+s)*DH+dh]
// MODE 1: store fp32 row-major + bias   outf[m*D+n]
// ---------------------------------------------------------------------------
#define TILE_B  16384
#define STAGE_B (4*TILE_B)
#define TG_SMEM (2*STAGE_B)
#define NCHUNK  (D_/64)

template<int MODE>
__global__ __launch_bounds__(256, 1) void tgemm(const __nv_bfloat16* __restrict__ Ahi,
                                                const __nv_bfloat16* __restrict__ Alo,
                                                const __nv_bfloat16* __restrict__ Bhi,
                                                const __nv_bfloat16* __restrict__ Blo,
                                                const float* __restrict__ bias,
                                                float* __restrict__ outf,
                                                __nv_bfloat16* __restrict__ ohi,
                                                __nv_bfloat16* __restrict__ olo)
{
    extern __shared__ char smem[];
    const uint32_t sb = smem_u32(smem);
    const int tid  = threadIdx.x;
    const int wid  = tid >> 5;
    const int lane = tid & 31;
    const int wm   = wid >> 2;
    const int wn   = wid & 3;
    const int m0   = blockIdx.y * 128;
    const int n0   = blockIdx.x * 128;

    const char* gsrc[4] = {
        (const char*)(Ahi + (size_t)m0 * D_),
        (const char*)(Alo + (size_t)m0 * D_),
        (const char*)(Bhi + (size_t)n0 * D_),
        (const char*)(Blo + (size_t)n0 * D_) };

    auto load_stage = [&](int chunk, uint32_t stage_base) {
        const uint32_t koff = (uint32_t)chunk * 128;
#pragma unroll
        for (int t = 0; t < 4; ++t) {
            const char* base = gsrc[t] + koff;
            const uint32_t dstt = stage_base + t * TILE_B;
#pragma unroll
            for (int it = 0; it < 4; ++it) {
                const int c = tid + it * 256;
                const int r = c >> 3;
                const int c16 = c & 7;
                cp16(dstt + swz((uint32_t)(r * 128 + c16 * 16)),
                     base + (size_t)r * (D_ * 2) + c16 * 16);
            }
        }
        cp_commit();
    };

    float acc[4][4][4];
#pragma unroll
    for (int i = 0; i < 4; i++)
#pragma unroll
        for (int j = 0; j < 4; j++)
#pragma unroll
            for (int q = 0; q < 4; q++) acc[i][j][q] = 0.f;

    load_stage(0, sb);

    for (int c = 0; c < NCHUNK; ++c) {
        cp_wait0();
        __syncthreads();
        const uint32_t cur = sb + (c & 1) * STAGE_B;
        if (c + 1 < NCHUNK) load_stage(c + 1, sb + ((c + 1) & 1) * STAGE_B);

        const uint32_t aHi = cur;
        const uint32_t aLo = cur + TILE_B;
        const uint32_t bHi = cur + 2 * TILE_B;
        const uint32_t bLo = cur + 3 * TILE_B;

#pragma unroll
        for (int ks = 0; ks < 4; ++ks) {
            uint32_t ahi[4][4], alo[4][4];
            {
                const int rA = wm * 64 + (lane & 15);
                const uint32_t colA = (uint32_t)(ks * 32 + (lane >> 4) * 16);
#pragma unroll
                for (int mf = 0; mf < 4; ++mf) {
                    const uint32_t off = swz((uint32_t)(rA + mf * 16) * 128 + colA);
                    ldsm4(ahi[mf][0], ahi[mf][1], ahi[mf][2], ahi[mf][3], aHi + off);
                    ldsm4(alo[mf][0], alo[mf][1], alo[mf][2], alo[mf][3], aLo + off);
                }
            }
            uint32_t bhi[4][2], blo[4][2];
            {
                const int t = lane >> 3;
                const int rB0 = wn * 32 + ((t >> 1) * 8) + (lane & 7);
                const uint32_t colB = (uint32_t)(ks * 32 + (t & 1) * 16);
#pragma unroll
                for (int p = 0; p < 2; ++p) {
                    const uint32_t off = swz((uint32_t)(rB0 + p * 16) * 128 + colB);
                    ldsm4(bhi[2*p][0], bhi[2*p][1], bhi[2*p+1][0], bhi[2*p+1][1], bHi + off);
                    ldsm4(blo[2*p][0], blo[2*p][1], blo[2*p+1][0], blo[2*p+1][1], bLo + off);
                }
            }
#pragma unroll
            for (int mf = 0; mf < 4; ++mf)
#pragma unroll
                for (int nf = 0; nf < 4; ++nf) {
                    mma16816(acc[mf][nf], ahi[mf], bhi[nf]);
                    mma16816(acc[mf][nf], ahi[mf], blo[nf]);
                    mma16816(acc[mf][nf], alo[mf], bhi[nf]);
                }
        }
        __syncthreads();
    }

    const int gid = lane >> 2, tig = lane & 3;
#pragma unroll
    for (int mf = 0; mf < 4; ++mf)
#pragma unroll
        for (int nf = 0; nf < 4; ++nf)
#pragma unroll
            for (int half = 0; half < 2; ++half) {
                const int m = m0 + wm * 64 + mf * 16 + gid + half * 8;
                const int n = n0 + wn * 32 + nf * 8 + tig * 2;
                float2 v = make_float2(acc[mf][nf][half*2], acc[mf][nf][half*2+1]);
                if (MODE == 1) {
                    v.x += bias[n]; v.y += bias[n+1];
                    *(float2*)(outf + (size_t)m * D_ + n) = v;
                } else {
                    const int b  = m >> 11;
                    const int s  = m & (S_ - 1);
                    const int h  = n >> 6;
                    const int dh = n & (DH_ - 1);
                    const size_t idx = ((size_t)(b * H_ + h) * S_ + s) * DH_ + dh;
                    __nv_bfloat16 h0 = __float2bfloat16(v.x);
                    __nv_bfloat16 h1 = __float2bfloat16(v.y);
                    __nv_bfloat16 l0 = __float2bfloat16(v.x - __bfloat162float(h0));
                    __nv_bfloat16 l1 = __float2bfloat16(v.y - __bfloat162float(h1));
                    *(__nv_bfloat162*)(ohi + idx) = __halves2bfloat162(h0, h1);
                    *(__nv_bfloat162*)(olo + idx) = __halves2bfloat162(l0, l1);
                }
            }
}

// ---------------------------------------------------------------------------
// HMMA flash attention, causal. 128 q-rows per CTA, 128-key tiles, 256 thr.
// Warp w owns q-rows w*16..w*16+15 (full 128 cols) -> softmax reductions stay
// in a 4-lane shfl quad. bf16x3 compensation on both Q·K^T and P·V.
// Writes ctx directly as bf16 hi/lo (row-major) for the out-projection.
// ---------------------------------------------------------------------------
#define SM_Q    0                       // QHI 16K + QLO 16K
#define SM_KV   32768                   // 2 stages x (KHI,KLO,VHI,VLO) 16K each
#define KV_STG  65536
#define ATT_SMEM (32768 + 2*KV_STG)     // 163840 B

__global__ __launch_bounds__(256, 1) void attn_tc()
{
    extern __shared__ char smem[];
    const uint32_t sb = smem_u32(smem);
    const int tid  = threadIdx.x;
    const int w    = tid >> 5;
    const int lane = tid & 31;
    const int gid  = lane >> 2;
    const int tig  = lane & 3;
    const int qt   = (int)(gridDim.x - 1 - blockIdx.x);   // heavy tiles first
    const int bh   = blockIdx.y;
    const int q0   = qt * 128;
    const int b    = bh >> 4;
    const int h    = bh & (H_ - 1);

    const size_t headoff = (size_t)bh * S_ * DH_;

    // ---- async load Q tile (hi/lo) ----
    {
        const char* qh = (const char*)(g_qhi + headoff + (size_t)q0 * DH_);
        const char* ql = (const char*)(g_qlo + headoff + (size_t)q0 * DH_);
#pragma unroll
        for (int it = 0; it < 4; ++it) {
            const int c = tid + it * 256;
            const int r = c >> 3, c16 = c & 7;
            const uint32_t off = swz((uint32_t)(r * 128 + c16 * 16));
            cp16(sb + SM_Q + off,         qh + r * 128 + c16 * 16);
            cp16(sb + SM_Q + 16384 + off, ql + r * 128 + c16 * 16);
        }
    }
    auto load_kv = [&](int kt, int stg) {
        const uint32_t base = sb + SM_KV + stg * KV_STG;
        const size_t g = headoff + (size_t)kt * 128 * DH_;
        const char* srcs[4] = { (const char*)(g_khi + g), (const char*)(g_klo + g),
                                (const char*)(g_vhi + g), (const char*)(g_vlo + g) };
#pragma unroll
        for (int t = 0; t < 4; ++t) {
#pragma unroll
            for (int it = 0; it < 4; ++it) {
                const int c = tid + it * 256;
                const int r = c >> 3, c16 = c & 7;
                cp16(base + t * 16384 + swz((uint32_t)(r * 128 + c16 * 16)),
                     srcs[t] + r * 128 + c16 * 16);
            }
        }
        cp_commit();
    };
    load_kv(0, 0);

    float m0v = -1e30f, m1v = -1e30f, l0v = 0.f, l1v = 0.f;
    float o[8][4];
#pragma unroll
    for (int i = 0; i < 8; i++)
#pragma unroll
        for (int j = 0; j < 4; j++) o[i][j] = 0.f;

    uint32_t qh[4][4], ql[4][4];
    const int qrow0 = q0 + w * 16 + gid;
    const int qrow1 = qrow0 + 8;
    const float SC = 0.18033688011112042f;   // (1/sqrt(64)) * log2(e)

    for (int kt = 0; kt <= qt; ++kt) {
        cp_wait0();
        __syncthreads();
        if (kt == 0) {
            // Q fragments once (rows w*16..+15, k = dh 0..63)
            const int rA = w * 16 + (lane & 15);
            const uint32_t colA = (uint32_t)((lane >> 4) * 16);
#pragma unroll
            for (int ks = 0; ks < 4; ++ks) {
                const uint32_t off = swz((uint32_t)rA * 128 + ks * 32 + colA);
                ldsm4(qh[ks][0], qh[ks][1], qh[ks][2], qh[ks][3], sb + SM_Q + off);
                ldsm4(ql[ks][0], ql[ks][1], ql[ks][2], ql[ks][3], sb + SM_Q + 16384 + off);
            }
        }
        if (kt < qt) load_kv(kt + 1, (kt + 1) & 1);

        const uint32_t cur = sb + SM_KV + (kt & 1) * KV_STG;
        const uint32_t KHI = cur, KLO = cur + 16384, VHI = cur + 32768, VLO = cur + 49152;
        const int k0 = kt * 128;

        // ---- S = Q @ K^T  (16 n8-frags per warp) ----
        float sacc[16][4];
#pragma unroll
        for (int i = 0; i < 16; i++)
#pragma unroll
            for (int j = 0; j < 4; j++) sacc[i][j] = 0.f;

#pragma unroll
        for (int ks = 0; ks < 4; ++ks) {
            const int t = lane >> 3;
            const uint32_t colB = (uint32_t)(ks * 32 + (t & 1) * 16);
#pragma unroll
            for (int ng = 0; ng < 8; ++ng) {
                const int rK = ng * 16 + ((t >> 1) * 8) + (lane & 7);
                const uint32_t off = swz((uint32_t)rK * 128 + colB);
                uint32_t kh[4], kl[4];
                ldsm4(kh[0], kh[1], kh[2], kh[3], KHI + off);
                ldsm4(kl[0], kl[1], kl[2], kl[3], KLO + off);
                mma16816(sacc[2*ng],   qh[ks], kh);
                mma16816(sacc[2*ng],   qh[ks], kl);
                mma16816(sacc[2*ng],   ql[ks], kh);
                mma16816(sacc[2*ng+1], qh[ks], kh + 2);
                mma16816(sacc[2*ng+1], qh[ks], kl + 2);
                mma16816(sacc[2*ng+1], ql[ks], kh + 2);
            }
        }

        // ---- scale (+ causal mask on diagonal tile), log2 domain ----
        if (kt == qt) {
#pragma unroll
            for (int nf = 0; nf < 16; ++nf) {
                const int col = k0 + nf * 8 + tig * 2;
                sacc[nf][0] = (col     > qrow0) ? -1e30f : sacc[nf][0] * SC;
                sacc[nf][1] = (col + 1 > qrow0) ? -1e30f : sacc[nf][1] * SC;
                sacc[nf][2] = (col     > qrow1) ? -1e30f : sacc[nf][2] * SC;
                sacc[nf][3] = (col + 1 > qrow1) ? -1e30f : sacc[nf][3] * SC;
            }
        } else {
#pragma unroll
            for (int nf = 0; nf < 16; ++nf)
#pragma unroll
                for (int j = 0; j < 4; ++j) sacc[nf][j] *= SC;
        }

        // ---- online softmax (rows gid / gid+8; reduce over tig quad) ----
        float rm0 = -1e30f, rm1 = -1e30f;
#pragma unroll
        for (int nf = 0; nf < 16; ++nf) {
            rm0 = fmaxf(rm0, fmaxf(sacc[nf][0], sacc[nf][1]));
            rm1 = fmaxf(rm1, fmaxf(sacc[nf][2], sacc[nf][3]));
        }
        rm0 = fmaxf(rm0, __shfl_xor_sync(0xffffffffu, rm0, 1));
        rm0 = fmaxf(rm0, __shfl_xor_sync(0xffffffffu, rm0, 2));
        rm1 = fmaxf(rm1, __shfl_xor_sync(0xffffffffu, rm1, 1));
        rm1 = fmaxf(rm1, __shfl_xor_sync(0xffffffffu, rm1, 2));
        const float mn0 = fmaxf(m0v, rm0);
        const float mn1 = fmaxf(m1v, rm1);
        const float al0 = ex2(m0v - mn0);
        const float al1 = ex2(m1v - mn1);
        float rs0 = 0.f, rs1 = 0.f;
#pragma unroll
        for (int nf = 0; nf < 16; ++nf) {
            sacc[nf][0] = ex2(sacc[nf][0] - mn0);
            sacc[nf][1] = ex2(sacc[nf][1] - mn0);
            sacc[nf][2] = ex2(sacc[nf][2] - mn1);
            sacc[nf][3] = ex2(sacc[nf][3] - mn1);
            rs0 += sacc[nf][0] + sacc[nf][1];
            rs1 += sacc[nf][2] + sacc[nf][3];
        }
        rs0 += __shfl_xor_sync(0xffffffffu, rs0, 1);
        rs0 += __shfl_xor_sync(0xffffffffu, rs0, 2);
        rs1 += __shfl_xor_sync(0xffffffffu, rs1, 1);
        rs1 += __shfl_xor_sync(0xffffffffu, rs1, 2);
        l0v = l0v * al0 + rs0;  m0v = mn0;
        l1v = l1v * al1 + rs1;  m1v = mn1;
#pragma unroll
        for (int nf = 0; nf < 8; ++nf) {
            o[nf][0] *= al0; o[nf][1] *= al0;
            o[nf][2] *= al1; o[nf][3] *= al1;
        }

        // ---- pack P into A-fragments (hi + residual lo), in registers ----
        uint32_t phA[8][4], plA[8][4];
#pragma unroll
        for (int ks2 = 0; ks2 < 8; ++ks2) {
#pragma unroll
            for (int q = 0; q < 4; ++q) {
                const int nf = 2 * ks2 + (q >> 1);
                const int e  = (q & 1) * 2;
                const float x = sacc[nf][e], y = sacc[nf][e + 1];
                const __nv_bfloat16 hx = __float2bfloat16(x);
                const __nv_bfloat16 hy = __float2bfloat16(y);
                phA[ks2][q] = packbf(hx, hy);
                plA[ks2][q] = packbf(__float2bfloat16(x - __bfloat162float(hx)),
                                     __float2bfloat16(y - __bfloat162float(hy)));
            }
        }

        // ---- O += P @ V  (V B-frags via trans-ldmatrix from [key][dh]) ----
        const int t = lane >> 3;
#pragma unroll
        for (int ks2 = 0; ks2 < 8; ++ks2) {
            const int kq = ks2 * 16 + (t & 1) * 8 + (lane & 7);
#pragma unroll
            for (int og = 0; og < 4; ++og) {
                const uint32_t off = swz((uint32_t)kq * 128 + og * 32 + (t >> 1) * 16);
                uint32_t vh[4], vl[4];
                ldsm4t(vh[0], vh[1], vh[2], vh[3], VHI + off);
                ldsm4t(vl[0], vl[1], vl[2], vl[3], VLO + off);
                mma16816(o[2*og],   phA[ks2], vh);
                mma16816(o[2*og],   phA[ks2], vl);
                mma16816(o[2*og],   plA[ks2], vh);
                mma16816(o[2*og+1], phA[ks2], vh + 2);
                mma16816(o[2*og+1], phA[ks2], vl + 2);
                mma16816(o[2*og+1], plA[ks2], vh + 2);
            }
        }
        __syncthreads();
    }

    // ---- normalize, write ctx as bf16 hi/lo row-major ----
    const float inv0 = 1.f / l0v;
    const float inv1 = 1.f / l1v;
#pragma unroll
    for (int nf = 0; nf < 8; ++nf) {
        const int dh = nf * 8 + tig * 2;
        {
            const float x = o[nf][0] * inv0, y = o[nf][1] * inv0;
            const size_t idx = ((size_t)(b * S_ + qrow0 - q0 + q0)) * D_ + h * DH_ + dh;
            const __nv_bfloat16 hx = __float2bfloat16(x), hy = __float2bfloat16(y);
            *(__nv_bfloat162*)(g_chi + (size_t)(b * S_ + qrow0) * D_ + h * DH_ + dh) =
                __halves2bfloat162(hx, hy);
            *(__nv_bfloat162*)(g_clo + (size_t)(b * S_ + qrow0) * D_ + h * DH_ + dh) =
                __halves2bfloat162(__float2bfloat16(x - __bfloat162float(hx)),
                                   __float2bfloat16(y - __bfloat162float(hy)));
            (void)idx;
        }
        {
            const float x = o[nf][2] * inv1, y = o[nf][3] * inv1;
            const __nv_bfloat16 hx = __float2bfloat16(x), hy = __float2bfloat16(y);
            *(__nv_bfloat162*)(g_chi + (size_t)(b * S_ + qrow1) * D_ + h * DH_ + dh) =
                __halves2bfloat162(hx, hy);
            *(__nv_bfloat162*)(g_clo + (size_t)(b * S_ + qrow1) * D_ + h * DH_ + dh) =
                __halves2bfloat162(__float2bfloat16(x - __bfloat162float(hx)),
                                   __float2bfloat16(y - __bfloat162float(hy)));
        }
    }
}

// ---------------------------------------------------------------------------
extern "C" void kernel_launch(void* const* d_in, const int* in_sizes, int n_in,
                              void* d_out, int out_size)
{
    const float* x  = (const float*)d_in[0];
    const float* Wq = (const float*)d_in[1];
    const float* Wk = (const float*)d_in[2];
    const float* Wv = (const float*)d_in[3];
    const float* Wo = (const float*)d_in[4];
    const float* bo = (const float*)d_in[5];
    float* out = (float*)d_out;

    __nv_bfloat16 *xhi, *xlo, *whi, *wlo, *chi, *clo;
    __nv_bfloat16 *qhi, *qlo, *khi, *klo, *vhi, *vlo;
    cudaGetSymbolAddress((void**)&xhi, g_xhi);
    cudaGetSymbolAddress((void**)&xlo, g_xlo);
    cudaGetSymbolAddress((void**)&whi, g_whi);
    cudaGetSymbolAddress((void**)&wlo, g_wlo);
    cudaGetSymbolAddress((void**)&chi, g_chi);
    cudaGetSymbolAddress((void**)&clo, g_clo);
    cudaGetSymbolAddress((void**)&qhi, g_qhi);
    cudaGetSymbolAddress((void**)&qlo, g_qlo);
    cudaGetSymbolAddress((void**)&khi, g_khi);
    cudaGetSymbolAddress((void**)&klo, g_klo);
    cudaGetSymbolAddress((void**)&vhi, g_vhi);
    cudaGetSymbolAddress((void**)&vlo, g_vlo);

    cudaFuncSetAttribute(tgemm<0>, cudaFuncAttributeMaxDynamicSharedMemorySize, TG_SMEM);
    cudaFuncSetAttribute(tgemm<1>, cudaFuncAttributeMaxDynamicSharedMemorySize, TG_SMEM);
    cudaFuncSetAttribute(attn_tc,  cudaFuncAttributeMaxDynamicSharedMemorySize, ATT_SMEM);

    const int nx = M_ * D_;
    const int nw = D_ * D_;
    split_bf16<<<nx/512, 256>>>(x,  xhi, xlo, nx);
    split_bf16<<<nw/512, 256>>>(Wq, whi + 0*(size_t)nw, wlo + 0*(size_t)nw, nw);
    split_bf16<<<nw/512, 256>>>(Wk, whi + 1*(size_t)nw, wlo + 1*(size_t)nw, nw);
    split_bf16<<<nw/512, 256>>>(Wv, whi + 2*(size_t)nw, wlo + 2*(size_t)nw, nw);
    split_bf16<<<nw/512, 256>>>(Wo, whi + 3*(size_t)nw, wlo + 3*(size_t)nw, nw);

    dim3 ggrid(D_/128, M_/128);   // (8, 32)
    tgemm<0><<<ggrid, 256, TG_SMEM>>>(xhi, xlo, whi + 0*(size_t)nw, wlo + 0*(size_t)nw,
                                      nullptr, nullptr, qhi, qlo);
    tgemm<0><<<ggrid, 256, TG_SMEM>>>(xhi, xlo, whi + 1*(size_t)nw, wlo + 1*(size_t)nw,
                                      nullptr, nullptr, khi, klo);
    tgemm<0><<<ggrid, 256, TG_SMEM>>>(xhi, xlo, whi + 2*(size_t)nw, wlo + 2*(size_t)nw,
                                      nullptr, nullptr, vhi, vlo);

    attn_tc<<<dim3(S_/128, B_*H_), 256, ATT_SMEM>>>();

    tgemm<1><<<ggrid, 256, TG_SMEM>>>(chi, clo, whi + 3*(size_t)nw, wlo + 3*(size_t)nw,
                                      bo, out, nullptr, nullptr);
}

// round 5
// speedup vs baseline: 3.6809x; 1.0327x over previous
#include <cuda_runtime.h>
#include <cuda_bf16.h>
#include <cstdint>

// Problem constants
#define B_  2
#define S_  2048
#define D_  1024
#define H_  16
#define DH_ 64
#define M_  (B_*S_)          // 4096 rows total

// ---------------------------------------------------------------------------
// Scratch (allocation-free __device__ globals), all bf16 hi/lo pairs
// ---------------------------------------------------------------------------
__device__ __nv_bfloat16 g_qhi[(size_t)B_*H_*S_*DH_];   // head-major
__device__ __nv_bfloat16 g_qlo[(size_t)B_*H_*S_*DH_];
__device__ __nv_bfloat16 g_khi[(size_t)B_*H_*S_*DH_];
__device__ __nv_bfloat16 g_klo[(size_t)B_*H_*S_*DH_];
__device__ __nv_bfloat16 g_vhi[(size_t)B_*H_*S_*DH_];
__device__ __nv_bfloat16 g_vlo[(size_t)B_*H_*S_*DH_];
__device__ __nv_bfloat16 g_chi[(size_t)M_*D_];          // ctx row-major
__device__ __nv_bfloat16 g_clo[(size_t)M_*D_];
__device__ __nv_bfloat16 g_xhi[(size_t)M_*D_];
__device__ __nv_bfloat16 g_xlo[(size_t)M_*D_];
__device__ __nv_bfloat16 g_whi[(size_t)4*D_*D_];
__device__ __nv_bfloat16 g_wlo[(size_t)4*D_*D_];

// ---------------------------------------------------------------------------
// PTX helpers (plain sm_80-class PTX: valid under compute_103)
// ---------------------------------------------------------------------------
__device__ __forceinline__ uint32_t smem_u32(const void* p) {
    uint32_t a;
    asm("{ .reg .u64 t; cvta.to.shared.u64 t, %1; cvt.u32.u64 %0, t; }"
        : "=r"(a) : "l"(p));
    return a;
}
__device__ __forceinline__ void cp16(uint32_t dst, const void* src) {
    asm volatile("cp.async.cg.shared.global [%0], [%1], 16;"
                 :: "r"(dst), "l"(src) : "memory");
}
__device__ __forceinline__ void cp_commit() {
    asm volatile("cp.async.commit_group;" ::: "memory");
}
__device__ __forceinline__ void cp_wait0() {
    asm volatile("cp.async.wait_group 0;" ::: "memory");
}
__device__ __forceinline__ void ldsm4(uint32_t& r0, uint32_t& r1, uint32_t& r2,
                                      uint32_t& r3, uint32_t addr) {
    asm volatile("ldmatrix.sync.aligned.m8n8.x4.shared.b16 {%0,%1,%2,%3}, [%4];"
                 : "=r"(r0), "=r"(r1), "=r"(r2), "=r"(r3) : "r"(addr));
}
__device__ __forceinline__ void ldsm4t(uint32_t& r0, uint32_t& r1, uint32_t& r2,
                                       uint32_t& r3, uint32_t addr) {
    asm volatile("ldmatrix.sync.aligned.m8n8.x4.trans.shared.b16 {%0,%1,%2,%3}, [%4];"
                 : "=r"(r0), "=r"(r1), "=r"(r2), "=r"(r3) : "r"(addr));
}
__device__ __forceinline__ void mma16816(float* c, const uint32_t* a, const uint32_t* b) {
    asm volatile(
        "mma.sync.aligned.m16n8k16.row.col.f32.bf16.bf16.f32 "
        "{%0,%1,%2,%3}, {%4,%5,%6,%7}, {%8,%9}, {%0,%1,%2,%3};"
        : "+f"(c[0]), "+f"(c[1]), "+f"(c[2]), "+f"(c[3])
        : "r"(a[0]), "r"(a[1]), "r"(a[2]), "r"(a[3]), "r"(b[0]), "r"(b[1]));
}
__device__ __forceinline__ float ex2(float x) {
    float y; asm("ex2.approx.ftz.f32 %0, %1;" : "=f"(y) : "f"(x)); return y;
}
// Swizzle<3,4,3>: XOR 16B-column bits [6:4] with row bits [9:7]
__device__ __forceinline__ uint32_t swz(uint32_t off) {
    return off ^ ((off >> 3) & 0x70);
}
__device__ __forceinline__ uint32_t packbf(__nv_bfloat16 a, __nv_bfloat16 b) {
    __nv_bfloat162 h = __halves2bfloat162(a, b);
    return *(uint32_t*)&h;
}

// ---------------------------------------------------------------------------
// fp32 -> bf16 hi/lo splits
// ---------------------------------------------------------------------------
__global__ void split_bf16(const float* __restrict__ src,
                           __nv_bfloat16* __restrict__ hi,
                           __nv_bfloat16* __restrict__ lo)
{
    const size_t i = ((size_t)blockIdx.x * blockDim.x + threadIdx.x) * 4;
    float4 v = *(const float4*)(src + i);
    __nv_bfloat16 h0 = __float2bfloat16(v.x), h1 = __float2bfloat16(v.y);
    __nv_bfloat16 h2 = __float2bfloat16(v.z), h3 = __float2bfloat16(v.w);
    *(__nv_bfloat162*)(hi + i)     = __halves2bfloat162(h0, h1);
    *(__nv_bfloat162*)(hi + i + 2) = __halves2bfloat162(h2, h3);
    *(__nv_bfloat162*)(lo + i) = __halves2bfloat162(
        __float2bfloat16(v.x - __bfloat162float(h0)),
        __float2bfloat16(v.y - __bfloat162float(h1)));
    *(__nv_bfloat162*)(lo + i + 2) = __halves2bfloat162(
        __float2bfloat16(v.z - __bfloat162float(h2)),
        __float2bfloat16(v.w - __bfloat162float(h3)));
}

// 4 weight matrices in one launch: blockIdx.y selects source
__global__ void split4_bf16(const float* __restrict__ a, const float* __restrict__ b,
                            const float* __restrict__ c, const float* __restrict__ d,
                            __nv_bfloat16* __restrict__ hi,
                            __nv_bfloat16* __restrict__ lo)
{
    const int w = blockIdx.y;
    const float* src = (w == 0) ? a : (w == 1) ? b : (w == 2) ? c : d;
    const size_t base = (size_t)w * D_ * D_;
    const size_t i = ((size_t)blockIdx.x * blockDim.x + threadIdx.x) * 4;
    float4 v = *(const float4*)(src + i);
    __nv_bfloat16 h0 = __float2bfloat16(v.x), h1 = __float2bfloat16(v.y);
    __nv_bfloat16 h2 = __float2bfloat16(v.z), h3 = __float2bfloat16(v.w);
    *(__nv_bfloat162*)(hi + base + i)     = __halves2bfloat162(h0, h1);
    *(__nv_bfloat162*)(hi + base + i + 2) = __halves2bfloat162(h2, h3);
    *(__nv_bfloat162*)(lo + base + i) = __halves2bfloat162(
        __float2bfloat16(v.x - __bfloat162float(h0)),
        __float2bfloat16(v.y - __bfloat162float(h1)));
    *(__nv_bfloat162*)(lo + base + i + 2) = __halves2bfloat162(
        __float2bfloat16(v.z - __bfloat162float(h2)),
        __float2bfloat16(v.w - __bfloat162float(h3)));
}

// ---------------------------------------------------------------------------
// HMMA bf16x3 GEMM: C[m,n] = sum_k A[m,k]*W[n,k]   (A,W split hi/lo)
// 128x256 CTA tile, BK=64, 256 threads (8 warps = 2m x 4n, warp tile 64x64).
// MODE 0: fused-QKV store to g_q/g_k/g_v (bf16 hi/lo, head-major); N=3072
// MODE 1: store fp32 row-major + bias
// ---------------------------------------------------------------------------
#define A_TB   16384                 // 128 x 128B
#define B_TB   32768                 // 256 x 128B
#define STAGE_B (2*A_TB + 2*B_TB)    // 96 KB
#define TG_SMEM (2*STAGE_B)          // 192 KB
#define NCHUNK  (D_/64)              // 16

template<int MODE>
__global__ __launch_bounds__(256, 1) void tgemm(const __nv_bfloat16* __restrict__ Ahi,
                                                const __nv_bfloat16* __restrict__ Alo,
                                                const __nv_bfloat16* __restrict__ Bhi,
                                                const __nv_bfloat16* __restrict__ Blo,
                                                const float* __restrict__ bias,
                                                float* __restrict__ outf)
{
    extern __shared__ char smem[];
    const uint32_t sb = smem_u32(smem);
    const int tid  = threadIdx.x;
    const int wid  = tid >> 5;
    const int lane = tid & 31;
    const int wm   = wid >> 2;          // 0..1   (64-row slab)
    const int wn   = wid & 3;           // 0..3   (64-col slab)
    const int m0   = blockIdx.y * 128;
    const int n0   = blockIdx.x * 256;

    const char* gA[2] = { (const char*)(Ahi + (size_t)m0 * D_),
                          (const char*)(Alo + (size_t)m0 * D_) };
    const char* gB[2] = { (const char*)(Bhi + (size_t)n0 * D_),
                          (const char*)(Blo + (size_t)n0 * D_) };

    auto load_stage = [&](int chunk, uint32_t stage) {
        const uint32_t koff = (uint32_t)chunk * 128;
#pragma unroll
        for (int t = 0; t < 2; ++t) {
            const char* base = gA[t] + koff;
            const uint32_t dstt = stage + t * A_TB;
#pragma unroll
            for (int it = 0; it < 4; ++it) {
                const int c = tid + it * 256;          // 0..1023
                const int r = c >> 3, c16 = c & 7;
                cp16(dstt + swz((uint32_t)(r * 128 + c16 * 16)),
                     base + (size_t)r * (D_ * 2) + c16 * 16);
            }
        }
#pragma unroll
        for (int t = 0; t < 2; ++t) {
            const char* base = gB[t] + koff;
            const uint32_t dstt = stage + 2 * A_TB + t * B_TB;
#pragma unroll
            for (int it = 0; it < 8; ++it) {
                const int c = tid + it * 256;          // 0..2047
                const int r = c >> 3, c16 = c & 7;
                cp16(dstt + swz((uint32_t)(r * 128 + c16 * 16)),
                     base + (size_t)r * (D_ * 2) + c16 * 16);
            }
        }
        cp_commit();
    };

    float acc[4][8][4];
#pragma unroll
    for (int i = 0; i < 4; i++)
#pragma unroll
        for (int j = 0; j < 8; j++)
#pragma unroll
            for (int q = 0; q < 4; q++) acc[i][j][q] = 0.f;

    load_stage(0, sb);

    for (int c = 0; c < NCHUNK; ++c) {
        cp_wait0();
        __syncthreads();
        const uint32_t cur = sb + (c & 1) * STAGE_B;
        if (c + 1 < NCHUNK) load_stage(c + 1, sb + ((c + 1) & 1) * STAGE_B);

        const uint32_t aHi = cur;
        const uint32_t aLo = cur + A_TB;
        const uint32_t bHi = cur + 2 * A_TB;
        const uint32_t bLo = cur + 2 * A_TB + B_TB;

#pragma unroll
        for (int ks = 0; ks < 4; ++ks) {
            // A fragments (4 x m16k16), hi + lo
            uint32_t ahi[4][4], alo[4][4];
            {
                const int rA = wm * 64 + (lane & 15);
                const uint32_t colA = (uint32_t)(ks * 32 + (lane >> 4) * 16);
#pragma unroll
                for (int mf = 0; mf < 4; ++mf) {
                    const uint32_t off = swz((uint32_t)(rA + mf * 16) * 128 + colA);
                    ldsm4(ahi[mf][0], ahi[mf][1], ahi[mf][2], ahi[mf][3], aHi + off);
                    ldsm4(alo[mf][0], alo[mf][1], alo[mf][2], alo[mf][3], aLo + off);
                }
            }
            // B: 4 groups of n16 (8 n8-frags total), transient
            const int t = lane >> 3;
            const uint32_t colB = (uint32_t)(ks * 32 + (t & 1) * 16);
#pragma unroll
            for (int ng = 0; ng < 4; ++ng) {
                const int rB = wn * 64 + ng * 16 + ((t >> 1) * 8) + (lane & 7);
                const uint32_t off = swz((uint32_t)rB * 128 + colB);
                uint32_t bh[4], bl[4];
                ldsm4(bh[0], bh[1], bh[2], bh[3], bHi + off);
                ldsm4(bl[0], bl[1], bl[2], bl[3], bLo + off);
#pragma unroll
                for (int mf = 0; mf < 4; ++mf) {
                    mma16816(acc[mf][2*ng],   ahi[mf], bh);
                    mma16816(acc[mf][2*ng],   ahi[mf], bl);
                    mma16816(acc[mf][2*ng],   alo[mf], bh);
                    mma16816(acc[mf][2*ng+1], ahi[mf], bh + 2);
                    mma16816(acc[mf][2*ng+1], ahi[mf], bl + 2);
                    mma16816(acc[mf][2*ng+1], alo[mf], bh + 2);
                }
            }
        }
        __syncthreads();
    }

    // ---- epilogue ----
    const int gid = lane >> 2, tig = lane & 3;
    __nv_bfloat16 *dhi = nullptr, *dlo = nullptr;
    if (MODE == 0) {
        const int sel = n0 >> 10;     // whole 256-col block within one of q/k/v
        dhi = (sel == 0) ? g_qhi : (sel == 1) ? g_khi : g_vhi;
        dlo = (sel == 0) ? g_qlo : (sel == 1) ? g_klo : g_vlo;
    }
#pragma unroll
    for (int mf = 0; mf < 4; ++mf)
#pragma unroll
        for (int nf = 0; nf < 8; ++nf)
#pragma unroll
            for (int half = 0; half < 2; ++half) {
                const int m = m0 + wm * 64 + mf * 16 + gid + half * 8;
                const int n = n0 + wn * 64 + nf * 8 + tig * 2;
                float2 v = make_float2(acc[mf][nf][half*2], acc[mf][nf][half*2+1]);
                if (MODE == 1) {
                    v.x += bias[n]; v.y += bias[n+1];
                    *(float2*)(outf + (size_t)m * D_ + n) = v;
                } else {
                    const int nl = n & (D_ - 1);
                    const int b  = m >> 11;
                    const int s  = m & (S_ - 1);
                    const int h  = nl >> 6;
                    const int dh = nl & (DH_ - 1);
                    const size_t idx = ((size_t)(b * H_ + h) * S_ + s) * DH_ + dh;
                    __nv_bfloat16 h0 = __float2bfloat16(v.x);
                    __nv_bfloat16 h1 = __float2bfloat16(v.y);
                    *(__nv_bfloat162*)(dhi + idx) = __halves2bfloat162(h0, h1);
                    *(__nv_bfloat162*)(dlo + idx) = __halves2bfloat162(
                        __float2bfloat16(v.x - __bfloat162float(h0)),
                        __float2bfloat16(v.y - __bfloat162float(h1)));
                }
            }
}

// ---------------------------------------------------------------------------
// HMMA flash attention, causal (unchanged from R4 — passed at 1.18e-5)
// ---------------------------------------------------------------------------
#define SM_Q    0
#define SM_KV   32768
#define KV_STG  65536
#define ATT_SMEM (32768 + 2*KV_STG)     // 163840 B

__global__ __launch_bounds__(256, 1) void attn_tc()
{
    extern __shared__ char smem[];
    const uint32_t sb = smem_u32(smem);
    const int tid  = threadIdx.x;
    const int w    = tid >> 5;
    const int lane = tid & 31;
    const int gid  = lane >> 2;
    const int tig  = lane & 3;
    const int qt   = (int)(gridDim.x - 1 - blockIdx.x);
    const int bh   = blockIdx.y;
    const int q0   = qt * 128;
    const int b    = bh >> 4;
    const int h    = bh & (H_ - 1);

    const size_t headoff = (size_t)bh * S_ * DH_;

    {
        const char* qh = (const char*)(g_qhi + headoff + (size_t)q0 * DH_);
        const char* ql = (const char*)(g_qlo + headoff + (size_t)q0 * DH_);
#pragma unroll
        for (int it = 0; it < 4; ++it) {
            const int c = tid + it * 256;
            const int r = c >> 3, c16 = c & 7;
            const uint32_t off = swz((uint32_t)(r * 128 + c16 * 16));
            cp16(sb + SM_Q + off,         qh + r * 128 + c16 * 16);
            cp16(sb + SM_Q + 16384 + off, ql + r * 128 + c16 * 16);
        }
    }
    auto load_kv = [&](int kt, int stg) {
        const uint32_t base = sb + SM_KV + stg * KV_STG;
        const size_t g = headoff + (size_t)kt * 128 * DH_;
        const char* srcs[4] = { (const char*)(g_khi + g), (const char*)(g_klo + g),
                                (const char*)(g_vhi + g), (const char*)(g_vlo + g) };
#pragma unroll
        for (int t = 0; t < 4; ++t) {
#pragma unroll
            for (int it = 0; it < 4; ++it) {
                const int c = tid + it * 256;
                const int r = c >> 3, c16 = c & 7;
                cp16(base + t * 16384 + swz((uint32_t)(r * 128 + c16 * 16)),
                     srcs[t] + r * 128 + c16 * 16);
            }
        }
        cp_commit();
    };
    load_kv(0, 0);

    float m0v = -1e30f, m1v = -1e30f, l0v = 0.f, l1v = 0.f;
    float o[8][4];
#pragma unroll
    for (int i = 0; i < 8; i++)
#pragma unroll
        for (int j = 0; j < 4; j++) o[i][j] = 0.f;

    uint32_t qh[4][4], ql[4][4];
    const int qrow0 = q0 + w * 16 + gid;
    const int qrow1 = qrow0 + 8;
    const float SC = 0.18033688011112042f;   // (1/sqrt(64)) * log2(e)

    for (int kt = 0; kt <= qt; ++kt) {
        cp_wait0();
        __syncthreads();
        if (kt == 0) {
            const int rA = w * 16 + (lane & 15);
            const uint32_t colA = (uint32_t)((lane >> 4) * 16);
#pragma unroll
            for (int ks = 0; ks < 4; ++ks) {
                const uint32_t off = swz((uint32_t)rA * 128 + ks * 32 + colA);
                ldsm4(qh[ks][0], qh[ks][1], qh[ks][2], qh[ks][3], sb + SM_Q + off);
                ldsm4(ql[ks][0], ql[ks][1], ql[ks][2], ql[ks][3], sb + SM_Q + 16384 + off);
            }
        }
        if (kt < qt) load_kv(kt + 1, (kt + 1) & 1);

        const uint32_t cur = sb + SM_KV + (kt & 1) * KV_STG;
        const uint32_t KHI = cur, KLO = cur + 16384, VHI = cur + 32768, VLO = cur + 49152;
        const int k0 = kt * 128;

        float sacc[16][4];
#pragma unroll
        for (int i = 0; i < 16; i++)
#pragma unroll
            for (int j = 0; j < 4; j++) sacc[i][j] = 0.f;

#pragma unroll
        for (int ks = 0; ks < 4; ++ks) {
            const int t = lane >> 3;
            const uint32_t colB = (uint32_t)(ks * 32 + (t & 1) * 16);
#pragma unroll
            for (int ng = 0; ng < 8; ++ng) {
                const int rK = ng * 16 + ((t >> 1) * 8) + (lane & 7);
                const uint32_t off = swz((uint32_t)rK * 128 + colB);
                uint32_t kh[4], kl[4];
                ldsm4(kh[0], kh[1], kh[2], kh[3], KHI + off);
                ldsm4(kl[0], kl[1], kl[2], kl[3], KLO + off);
                mma16816(sacc[2*ng],   qh[ks], kh);
                mma16816(sacc[2*ng],   qh[ks], kl);
                mma16816(sacc[2*ng],   ql[ks], kh);
                mma16816(sacc[2*ng+1], qh[ks], kh + 2);
                mma16816(sacc[2*ng+1], qh[ks], kl + 2);
                mma16816(sacc[2*ng+1], ql[ks], kh + 2);
            }
        }

        if (kt == qt) {
#pragma unroll
            for (int nf = 0; nf < 16; ++nf) {
                const int col = k0 + nf * 8 + tig * 2;
                sacc[nf][0] = (col     > qrow0) ? -1e30f : sacc[nf][0] * SC;
                sacc[nf][1] = (col + 1 > qrow0) ? -1e30f : sacc[nf][1] * SC;
                sacc[nf][2] = (col     > qrow1) ? -1e30f : sacc[nf][2] * SC;
                sacc[nf][3] = (col + 1 > qrow1) ? -1e30f : sacc[nf][3] * SC;
            }
        } else {
#pragma unroll
            for (int nf = 0; nf < 16; ++nf)
#pragma unroll
                for (int j = 0; j < 4; ++j) sacc[nf][j] *= SC;
        }

        float rm0 = -1e30f, rm1 = -1e30f;
#pragma unroll
        for (int nf = 0; nf < 16; ++nf) {
            rm0 = fmaxf(rm0, fmaxf(sacc[nf][0], sacc[nf][1]));
            rm1 = fmaxf(rm1, fmaxf(sacc[nf][2], sacc[nf][3]));
        }
        rm0 = fmaxf(rm0, __shfl_xor_sync(0xffffffffu, rm0, 1));
        rm0 = fmaxf(rm0, __shfl_xor_sync(0xffffffffu, rm0, 2));
        rm1 = fmaxf(rm1, __shfl_xor_sync(0xffffffffu, rm1, 1));
        rm1 = fmaxf(rm1, __shfl_xor_sync(0xffffffffu, rm1, 2));
        const float mn0 = fmaxf(m0v, rm0);
        const float mn1 = fmaxf(m1v, rm1);
        const float al0 = ex2(m0v - mn0);
        const float al1 = ex2(m1v - mn1);
        float rs0 = 0.f, rs1 = 0.f;
#pragma unroll
        for (int nf = 0; nf < 16; ++nf) {
            sacc[nf][0] = ex2(sacc[nf][0] - mn0);
            sacc[nf][1] = ex2(sacc[nf][1] - mn0);
            sacc[nf][2] = ex2(sacc[nf][2] - mn1);
            sacc[nf][3] = ex2(sacc[nf][3] - mn1);
            rs0 += sacc[nf][0] + sacc[nf][1];
            rs1 += sacc[nf][2] + sacc[nf][3];
        }
        rs0 += __shfl_xor_sync(0xffffffffu, rs0, 1);
        rs0 += __shfl_xor_sync(0xffffffffu, rs0, 2);
        rs1 += __shfl_xor_sync(0xffffffffu, rs1, 1);
        rs1 += __shfl_xor_sync(0xffffffffu, rs1, 2);
        l0v = l0v * al0 + rs0;  m0v = mn0;
        l1v = l1v * al1 + rs1;  m1v = mn1;
#pragma unroll
        for (int nf = 0; nf < 8; ++nf) {
            o[nf][0] *= al0; o[nf][1] *= al0;
            o[nf][2] *= al1; o[nf][3] *= al1;
        }

        uint32_t phA[8][4], plA[8][4];
#pragma unroll
        for (int ks2 = 0; ks2 < 8; ++ks2) {
#pragma unroll
            for (int q = 0; q < 4; ++q) {
                const int nf = 2 * ks2 + (q >> 1);
                const int e  = (q & 1) * 2;
                const float x = sacc[nf][e], y = sacc[nf][e + 1];
                const __nv_bfloat16 hx = __float2bfloat16(x);
                const __nv_bfloat16 hy = __float2bfloat16(y);
                phA[ks2][q] = packbf(hx, hy);
                plA[ks2][q] = packbf(__float2bfloat16(x - __bfloat162float(hx)),
                                     __float2bfloat16(y - __bfloat162float(hy)));
            }
        }

        const int t = lane >> 3;
#pragma unroll
        for (int ks2 = 0; ks2 < 8; ++ks2) {
            const int kq = ks2 * 16 + (t & 1) * 8 + (lane & 7);
#pragma unroll
            for (int og = 0; og < 4; ++og) {
                const uint32_t off = swz((uint32_t)kq * 128 + og * 32 + (t >> 1) * 16);
                uint32_t vh[4], vl[4];
                ldsm4t(vh[0], vh[1], vh[2], vh[3], VHI + off);
                ldsm4t(vl[0], vl[1], vl[2], vl[3], VLO + off);
                mma16816(o[2*og],   phA[ks2], vh);
                mma16816(o[2*og],   phA[ks2], vl);
                mma16816(o[2*og],   plA[ks2], vh);
                mma16816(o[2*og+1], phA[ks2], vh + 2);
                mma16816(o[2*og+1], phA[ks2], vl + 2);
                mma16816(o[2*og+1], plA[ks2], vh + 2);
            }
        }
        __syncthreads();
    }

    const float inv0 = 1.f / l0v;
    const float inv1 = 1.f / l1v;
#pragma unroll
    for (int nf = 0; nf < 8; ++nf) {
        const int dh = nf * 8 + tig * 2;
        {
            const float x = o[nf][0] * inv0, y = o[nf][1] * inv0;
            const __nv_bfloat16 hx = __float2bfloat16(x), hy = __float2bfloat16(y);
            *(__nv_bfloat162*)(g_chi + (size_t)(b * S_ + qrow0) * D_ + h * DH_ + dh) =
                __halves2bfloat162(hx, hy);
            *(__nv_bfloat162*)(g_clo + (size_t)(b * S_ + qrow0) * D_ + h * DH_ + dh) =
                __halves2bfloat162(__float2bfloat16(x - __bfloat162float(hx)),
                                   __float2bfloat16(y - __bfloat162float(hy)));
        }
        {
            const float x = o[nf][2] * inv1, y = o[nf][3] * inv1;
            const __nv_bfloat16 hx = __float2bfloat16(x), hy = __float2bfloat16(y);
            *(__nv_bfloat162*)(g_chi + (size_t)(b * S_ + qrow1) * D_ + h * DH_ + dh) =
                __halves2bfloat162(hx, hy);
            *(__nv_bfloat162*)(g_clo + (size_t)(b * S_ + qrow1) * D_ + h * DH_ + dh) =
                __halves2bfloat162(__float2bfloat16(x - __bfloat162float(hx)),
                                   __float2bfloat16(y - __bfloat162float(hy)));
        }
    }
}

// ---------------------------------------------------------------------------
extern "C" void kernel_launch(void* const* d_in, const int* in_sizes, int n_in,
                              void* d_out, int out_size)
{
    const float* x  = (const float*)d_in[0];
    const float* Wq = (const float*)d_in[1];
    const float* Wk = (const float*)d_in[2];
    const float* Wv = (const float*)d_in[3];
    const float* Wo = (const float*)d_in[4];
    const float* bo = (const float*)d_in[5];
    float* out = (float*)d_out;

    __nv_bfloat16 *xhi, *xlo, *whi, *wlo, *chi, *clo;
    cudaGetSymbolAddress((void**)&xhi, g_xhi);
    cudaGetSymbolAddress((void**)&xlo, g_xlo);
    cudaGetSymbolAddress((void**)&whi, g_whi);
    cudaGetSymbolAddress((void**)&wlo, g_wlo);
    cudaGetSymbolAddress((void**)&chi, g_chi);
    cudaGetSymbolAddress((void**)&clo, g_clo);

    cudaFuncSetAttribute(tgemm<0>, cudaFuncAttributeMaxDynamicSharedMemorySize, TG_SMEM);
    cudaFuncSetAttribute(tgemm<1>, cudaFuncAttributeMaxDynamicSharedMemorySize, TG_SMEM);
    cudaFuncSetAttribute(attn_tc,  cudaFuncAttributeMaxDynamicSharedMemorySize, ATT_SMEM);

    const int nx = M_ * D_;     // 4M
    const int nw = D_ * D_;     // 1M
    split_bf16<<<nx/1024, 256>>>(x, xhi, xlo);
    split4_bf16<<<dim3(nw/1024, 4), 256>>>(Wq, Wk, Wv, Wo, whi, wlo);

    // fused QKV projection: N = 3072 against stacked Wq|Wk|Wv
    tgemm<0><<<dim3(3*D_/256, M_/128), 256, TG_SMEM>>>(xhi, xlo, whi, wlo,
                                                       nullptr, nullptr);

    attn_tc<<<dim3(S_/128, B_*H_), 256, ATT_SMEM>>>();

    tgemm<1><<<dim3(D_/256, M_/128), 256, TG_SMEM>>>(chi, clo,
                                                     whi + 3*(size_t)nw, wlo + 3*(size_t)nw,
                                                     bo, out);
}